// round 5
// baseline (speedup 1.0000x reference)
#include <cuda_runtime.h>
#include <mma.h>

using namespace nvcuda;

#define NRW 65536
#define HD  256

// ---------------- static device buffers --------------------------------------
__device__ __align__(256) float g_Xp[NRW * 32];             // padded input (cols 20..31 = 0)
__device__ __align__(256) float g_Wih0[1024 * 32];          // padded W_ih_00
__device__ __align__(256) float g_biasRep[4][16 * 1024];    // 16 replicated rows of (b_ih+b_hh)
__device__ __align__(256) float g_G[(size_t)NRW * 1024];    // input preactivations (+bias)
__device__ __align__(256) float g_Ybuf[3][(size_t)NRW * HD];
__device__ unsigned g_rdy[32];                              // per-row-group ready counters

typedef wmma::fragment<wmma::matrix_a, 16, 16, 8, wmma::precision::tf32, wmma::row_major> FragA;
typedef wmma::fragment<wmma::matrix_b, 16, 16, 8, wmma::precision::tf32, wmma::col_major> FragB;
typedef wmma::fragment<wmma::accumulator, 16, 16, 8, float> FragC;

__device__ __forceinline__ float sigf(float x) { return 1.0f / (1.0f + __expf(-x)); }

__device__ __forceinline__ void splitA(FragA& h, FragA& l) {
#pragma unroll
    for (int i = 0; i < h.num_elements; i++) {
        float v = h.x[i];
        float hh = wmma::__float_to_tf32(v);
        l.x[i] = wmma::__float_to_tf32(v - hh);
        h.x[i] = hh;
    }
}
__device__ __forceinline__ void splitB(FragB& h, FragB& l) {
#pragma unroll
    for (int i = 0; i < h.num_elements; i++) {
        float v = h.x[i];
        float hh = wmma::__float_to_tf32(v);
        l.x[i] = wmma::__float_to_tf32(v - hh);
        h.x[i] = hh;
    }
}

// 3xTF32 K-loop used by the head kernel
__device__ __forceinline__ void kloop3(FragC& acc, const float* __restrict__ A, int lda,
                                       const float* __restrict__ B, int ldb, int K) {
    for (int k = 0; k < K; k += 8) {
        FragA ah, al;
        FragB bh, bl;
        wmma::load_matrix_sync(ah, A + k, lda);
        wmma::load_matrix_sync(bh, B + k, ldb);
        splitA(ah, al);
        splitB(bh, bl);
        wmma::mma_sync(acc, ah, bh, acc);
        wmma::mma_sync(acc, ah, bl, acc);
        wmma::mma_sync(acc, al, bh, acc);
    }
}

// ---------------- prep: pad X / W_ih_00, replicated bias rows ----------------
__global__ void k_prep(const float* __restrict__ x, const float* __restrict__ wih0,
                       const float* __restrict__ bi0, const float* __restrict__ bh0,
                       const float* __restrict__ bi1, const float* __restrict__ bh1,
                       const float* __restrict__ bi2, const float* __restrict__ bh2,
                       const float* __restrict__ bi3, const float* __restrict__ bh3) {
    int tid = blockIdx.x * blockDim.x + threadIdx.x;
    int nt = gridDim.x * blockDim.x;
    for (int i = tid; i < NRW * 20; i += nt)
        g_Xp[(size_t)(i / 20) * 32 + (i % 20)] = x[i];
    for (int i = tid; i < 1024 * 20; i += nt)
        g_Wih0[(i / 20) * 32 + (i % 20)] = wih0[i];
    for (int i = tid; i < 16 * 1024; i += nt) {
        int c = i % 1024;
        g_biasRep[0][i] = bi0[c] + bh0[c];
        g_biasRep[1][i] = bi1[c] + bh1[c];
        g_biasRep[2][i] = bi2[c] + bh2[c];
        g_biasRep[3][i] = bi3[c] + bh3[c];
    }
}

// ---------------- bulk input projection: G = X @ W^T + bias ------------------
// grid (8, 512), block 256. BM=BN=128, BK=32, warp layout 4x2 (32x64 per warp).
template <int K>
__global__ void __launch_bounds__(256, 1)
bulk_k(const float* __restrict__ X, const float* __restrict__ W,
       const float* __restrict__ bR, float* __restrict__ G) {
    __shared__ float sA[128 * 40];
    __shared__ float sB[128 * 40];
    const int n0 = blockIdx.x * 128;
    const size_t m0 = (size_t)blockIdx.y * 128;
    const int w = threadIdx.x >> 5;
    const int wr = (w >> 1) * 32;
    const int wc = (w & 1) * 64;

    FragC acc[2][4];
#pragma unroll
    for (int a = 0; a < 2; a++)
#pragma unroll
        for (int b = 0; b < 4; b++) wmma::fill_fragment(acc[a][b], 0.0f);

    for (int k0 = 0; k0 < K; k0 += 32) {
        __syncthreads();
        for (int i = threadIdx.x; i < 128 * 32; i += 256) {
            int r = i >> 5, ci = i & 31;
            sA[r * 40 + ci] = X[(m0 + r) * K + k0 + ci];
            sB[r * 40 + ci] = W[(size_t)(n0 + r) * K + k0 + ci];
        }
        __syncthreads();
#pragma unroll
        for (int kk = 0; kk < 32; kk += 8) {
            FragA ah[2], al[2];
#pragma unroll
            for (int a = 0; a < 2; a++) {
                wmma::load_matrix_sync(ah[a], &sA[(wr + a * 16) * 40 + kk], 40);
                splitA(ah[a], al[a]);
            }
#pragma unroll
            for (int b = 0; b < 4; b++) {
                FragB bh, bl;
                wmma::load_matrix_sync(bh, &sB[(wc + b * 16) * 40 + kk], 40);
                splitB(bh, bl);
#pragma unroll
                for (int a = 0; a < 2; a++) {
                    wmma::mma_sync(acc[a][b], ah[a], bh, acc[a][b]);
                    wmma::mma_sync(acc[a][b], ah[a], bl, acc[a][b]);
                    wmma::mma_sync(acc[a][b], al[a], bh, acc[a][b]);
                }
            }
        }
    }
#pragma unroll
    for (int b = 0; b < 4; b++) {
        FragC bf;
        wmma::load_matrix_sync(bf, bR + n0 + wc + b * 16, 1024, wmma::mem_row_major);
#pragma unroll
        for (int a = 0; a < 2; a++) {
#pragma unroll
            for (int i = 0; i < bf.num_elements; i++) acc[a][b].x[i] += bf.x[i];
            wmma::store_matrix_sync(G + (m0 + wr + a * 16) * 1024 + n0 + wc + b * 16,
                                    acc[a][b], 1024, wmma::mem_row_major);
        }
    }
}

// ---------------- persistent sequential LSTM (h-recurrence only) -------------
// TM=128 rows/block, 8 warps; warp = 16 rows x (4 gates x TH cols). Whh slice in
// smem for the whole layer. Gates accumulate in register fragments; elementwise
// is fully register-resident via positional fragment correspondence.
template <int STEPS, int BEFF, int TH>
__global__ void __launch_bounds__(256, 1)
seq_k(const float* __restrict__ Whh, const float* __restrict__ G,
      float* __restrict__ Y, unsigned* __restrict__ rdy) {
    constexpr int C = 256 / TH;     // column groups
    constexpr int NHC = TH / 16;    // 16-wide h chunks per gate
    constexpr int NB = 4 * NHC;     // accumulator subtiles per warp
    constexpr int LDW = 264;
    constexpr int TM = 128;
    extern __shared__ float sW[];   // [4*TH][LDW]

    const int rm = blockIdx.x / C;
    const int cg = blockIdx.x % C;
    const int m0 = rm * TM;
    const int j0 = cg * TH;
    const int w = threadIdx.x >> 5;

    // stage Whh slice: smem row (gate*TH + hl) = W row (gate*256 + j0 + hl)
    for (int idx = threadIdx.x; idx < 4 * TH * 64; idx += 256) {
        const int r = idx >> 6;
        const int k4 = idx & 63;
        const int gate = r / TH;
        const int hl = r % TH;
        const float4 v = *(const float4*)(Whh + (size_t)(gate * 256 + j0 + hl) * 256 + k4 * 4);
        *(float4*)(sW + r * LDW + k4 * 4) = v;
    }
    __syncthreads();

    float cst[NHC * 8];
#pragma unroll
    for (int q = 0; q < NHC * 8; q++) cst[q] = 0.0f;

    for (int t = 0; t < STEPS; t++) {
        const size_t wrow = (size_t)t * BEFF + m0 + w * 16;

        if (t) {
            if (threadIdx.x == 0) {
                const unsigned tgt = (unsigned)C * (unsigned)t;
                while (*(volatile unsigned*)(rdy + rm) < tgt) __nanosleep(20);
                __threadfence();
            }
            __syncthreads();
        }

        // init accumulators from G (bias already folded in)
        FragC acc[NB];
#pragma unroll
        for (int b = 0; b < NB; b++) {
            const int gate = b / NHC;
            const int hc = b % NHC;
            wmma::load_matrix_sync(acc[b], G + wrow * 1024 + gate * 256 + j0 + hc * 16,
                                   1024, wmma::mem_row_major);
        }

        if (t) {
            const float* Ab = Y + (wrow - BEFF) * HD;   // h_{t-1}, this warp's rows
#pragma unroll 4
            for (int k0 = 0; k0 < HD; k0 += 8) {
                FragA ah, al;
                wmma::load_matrix_sync(ah, Ab + k0, HD);
                splitA(ah, al);
#pragma unroll
                for (int b = 0; b < NB; b++) {
                    FragB bh, bl;
                    wmma::load_matrix_sync(bh, sW + (b * 16) * LDW + k0, LDW);
                    splitB(bh, bl);
                    wmma::mma_sync(acc[b], ah, bh, acc[b]);
                    wmma::mma_sync(acc[b], ah, bl, acc[b]);
                    wmma::mma_sync(acc[b], al, bh, acc[b]);
                }
            }
        }

        // elementwise in registers; overwrite gate-i fragments with h, store
#pragma unroll
        for (int hc = 0; hc < NHC; hc++) {
#pragma unroll
            for (int e = 0; e < 8; e++) {
                const float pi = acc[0 * NHC + hc].x[e];
                const float pf = acc[1 * NHC + hc].x[e];
                const float pg = acc[2 * NHC + hc].x[e];
                const float po = acc[3 * NHC + hc].x[e];
                const float cn = sigf(pf) * cst[hc * 8 + e] + sigf(pi) * tanhf(pg);
                cst[hc * 8 + e] = cn;
                acc[hc].x[e] = sigf(po) * tanhf(cn);
            }
            wmma::store_matrix_sync(Y + wrow * HD + j0 + hc * 16, acc[hc],
                                    HD, wmma::mem_row_major);
        }

        __syncthreads();
        if (threadIdx.x == 0) {
            __threadfence();
            atomicAdd(rdy + rm, 1u);
        }
    }

    // reset counter for the next layer launch
    if (cg == 0 && threadIdx.x == 0) {
        const unsigned fin = (unsigned)C * (unsigned)STEPS;
        while (*(volatile unsigned*)(rdy + rm) < fin) __nanosleep(20);
        *(volatile unsigned*)(rdy + rm) = 0u;
        __threadfence();
    }
}

// ---------------- head: out = tanh((Y2+Y1) @ mlp_w^T + b) @ ad_w^T + ad_b ----
__global__ void __launch_bounds__(256, 2)
head_k(const float* __restrict__ Y2, const float* __restrict__ Y1,
       const float* __restrict__ mlpw, const float* __restrict__ mlpb,
       const float* __restrict__ adw, const float* __restrict__ adb,
       float* __restrict__ out) {
    __shared__ float sx[16][256];
    __shared__ float sh[16][256];
    __shared__ float so[16][48];

    const int warp = threadIdx.x >> 5;
    const size_t m0 = (size_t)blockIdx.x * 16;

    for (int e = threadIdx.x; e < 16 * 256; e += 256) {
        const size_t gi = m0 * 256 + e;
        sx[e / 256][e % 256] = Y2[gi] + Y1[gi];
    }
    __syncthreads();

    for (int st = warp; st < 16; st += 8) {
        FragC acc;
        wmma::fill_fragment(acc, 0.0f);
        kloop3(acc, &sx[0][0], 256, mlpw + (size_t)(st * 16) * 256, 256, 256);
        wmma::store_matrix_sync(&sh[0][st * 16], acc, 256, wmma::mem_row_major);
    }
    __syncthreads();
    for (int e = threadIdx.x; e < 16 * 256; e += 256)
        sh[e / 256][e % 256] = tanhf(sh[e / 256][e % 256] + mlpb[e % 256]);
    __syncthreads();

    if (warp < 3) {
        FragC acc;
        wmma::fill_fragment(acc, 0.0f);
        kloop3(acc, &sh[0][0], 256, adw + (size_t)(warp * 16) * 256, 256, 256);
        wmma::store_matrix_sync(&so[0][warp * 16], acc, 48, wmma::mem_row_major);
    }
    __syncthreads();
    for (int e = threadIdx.x; e < 16 * 48; e += 256)
        out[m0 * 48 + e] = so[e / 48][e % 48] + adb[e % 48];
}

// ---------------- host -------------------------------------------------------
extern "C" void kernel_launch(void* const* d_in, const int* in_sizes, int n_in,
                              void* d_out, int out_size) {
    const float* X     = (const float*)d_in[0];
    const float* Wih00 = (const float*)d_in[1];
    const float* Whh00 = (const float*)d_in[2];
    const float* bih00 = (const float*)d_in[3];
    const float* bhh00 = (const float*)d_in[4];
    const float* Wih01 = (const float*)d_in[5];
    const float* Whh01 = (const float*)d_in[6];
    const float* bih01 = (const float*)d_in[7];
    const float* bhh01 = (const float*)d_in[8];
    const float* Wih10 = (const float*)d_in[9];
    const float* Whh10 = (const float*)d_in[10];
    const float* bih10 = (const float*)d_in[11];
    const float* bhh10 = (const float*)d_in[12];
    const float* Wih11 = (const float*)d_in[13];
    const float* Whh11 = (const float*)d_in[14];
    const float* bih11 = (const float*)d_in[15];
    const float* bhh11 = (const float*)d_in[16];
    const float* mlpw  = (const float*)d_in[17];
    const float* mlpb  = (const float*)d_in[18];
    const float* adw   = (const float*)d_in[19];
    const float* adb   = (const float*)d_in[20];
    float* out = (float*)d_out;

    float *Xp, *Wih0p, *bRp, *Gp, *Yb;
    unsigned* rdyp;
    cudaGetSymbolAddress((void**)&Xp, g_Xp);
    cudaGetSymbolAddress((void**)&Wih0p, g_Wih0);
    cudaGetSymbolAddress((void**)&bRp, g_biasRep);
    cudaGetSymbolAddress((void**)&Gp, g_G);
    cudaGetSymbolAddress((void**)&Yb, g_Ybuf);
    cudaGetSymbolAddress((void**)&rdyp, g_rdy);
    float* Y0 = Yb;
    float* Y1 = Yb + (size_t)NRW * HD;
    float* Y2 = Yb + 2 * (size_t)NRW * HD;

    const int smem16 = 4 * 16 * 264 * 4;   // 67.6 KB
    const int smem32 = 4 * 32 * 264 * 4;   // 135 KB
    cudaFuncSetAttribute((const void*)seq_k<256, 256, 16>,
                         cudaFuncAttributeMaxDynamicSharedMemorySize, smem16);
    cudaFuncSetAttribute((const void*)seq_k<128, 512, 16>,
                         cudaFuncAttributeMaxDynamicSharedMemorySize, smem16);
    cudaFuncSetAttribute((const void*)seq_k<64, 1024, 16>,
                         cudaFuncAttributeMaxDynamicSharedMemorySize, smem16);
    cudaFuncSetAttribute((const void*)seq_k<32, 2048, 32>,
                         cudaFuncAttributeMaxDynamicSharedMemorySize, smem32);

    k_prep<<<512, 256>>>(X, Wih00, bih00, bhh00, bih01, bhh01,
                         bih10, bhh10, bih11, bhh11);

    dim3 bgrid(8, 512);

    // ---- group 0 ----
    bulk_k<32><<<bgrid, 256>>>(Xp, Wih0p, bRp + 0 * 16 * 1024, Gp);
    seq_k<256, 256, 16><<<32, 256, smem16>>>(Whh00, Gp, Y0, rdyp);

    bulk_k<256><<<bgrid, 256>>>(Y0, Wih01, bRp + 1 * 16 * 1024, Gp);
    seq_k<128, 512, 16><<<64, 256, smem16>>>(Whh01, Gp, Y1, rdyp);

    // ---- group 1 ----
    bulk_k<256><<<bgrid, 256>>>(Y1, Wih10, bRp + 2 * 16 * 1024, Gp);
    seq_k<64, 1024, 16><<<128, 256, smem16>>>(Whh10, Gp, Y0, rdyp);

    bulk_k<256><<<bgrid, 256>>>(Y0, Wih11, bRp + 3 * 16 * 1024, Gp);
    seq_k<32, 2048, 32><<<128, 256, smem32>>>(Whh11, Gp, Y2, rdyp);

    // head: (Y2 + Y1) -> tanh(mlp) -> adapter
    head_k<<<NRW / 16, 256>>>(Y2, Y1, mlpw, mlpb, adw, adb, out);
}